// round 5
// baseline (speedup 1.0000x reference)
#include <cuda_runtime.h>
#include <math.h>

// Problem constants
#define SQ    2048
#define SQ2   4096
#define HIDN  1024
#define NHEAD 8
#define HDIM  128
#define INTERN 4096

// ---------------- scratch (device globals; no allocations allowed) ----------------
__device__ float g_h   [SQ  * HIDN];                 // normed activations (reused)
__device__ float g_h1  [SQ  * HIDN];                 // post-attn residual
__device__ float g_qc  [NHEAD * SQ2 * HDIM];         // concat pre-RoPE q  [h][e*S+s][d]
__device__ float g_kc  [NHEAD * SQ2 * HDIM];         // concat pre-RoPE k
__device__ float g_vc  [NHEAD * SQ2 * HDIM];         // concat v
__device__ float g_qr  [NHEAD * SQ  * HDIM];         // RoPE'd q (per expert, reused)
__device__ float g_kr  [NHEAD * SQ  * HDIM];         // RoPE'd k
__device__ float g_scores[(size_t)NHEAD * SQ2 * SQ2];// attention scores (512MB, reused)
__device__ float g_attnM[SQ2 * HIDN];                // head-merged attention out
__device__ float g_gate[SQ * INTERN];
__device__ float g_up  [SQ * INTERN];
__device__ float g_oute[2 * SQ * HIDN];              // per-expert layer output

// ---------------- generic batched tiled SGEMM ----------------
// C[bz] = alpha * A[bz] @ op(B[bz]) (+ MASK) (+ ADD), 128x128x16 tiles, 8x8/thread.
// transB: B is (N x K) row-major, compute A @ B^T.
// All M,N multiples of 128; K multiple of 16 (true for every call here).
__global__ void __launch_bounds__(256) sgemm_kernel(
    const float* __restrict__ A, const float* __restrict__ B, float* __restrict__ C,
    const float* __restrict__ ADD, const float* __restrict__ MASK,
    int K, int lda, int ldb, int ldc, int mld,
    long long sA, long long sB, long long sC,
    float alpha, int transB)
{
    int bz = blockIdx.z;
    A += (long long)bz * sA;
    B += (long long)bz * sB;
    C += (long long)bz * sC;

    __shared__ float As[16][128];
    __shared__ float Bs[16][128];

    int tid  = threadIdx.x;
    int tx   = tid & 15;          // 0..15 -> col group
    int ty   = tid >> 4;          // 0..15 -> row group
    int row0 = blockIdx.y << 7;
    int col0 = blockIdx.x << 7;

    float acc[8][8];
#pragma unroll
    for (int i = 0; i < 8; i++)
#pragma unroll
        for (int j = 0; j < 8; j++) acc[i][j] = 0.0f;

    // A tile loader: 128 rows x 16 k = 2 float4 per thread (same row, k and k+4... use aK*8)
    int aRow = tid >> 1, aK = (tid & 1) << 3;        // aK in {0,8}: load k0+aK .. k0+aK+7
    // B tile loaders
    int bKn = tid >> 4, bNn = (tid & 15) << 3;       // NN: row 0..15, 8 cols
    int bNt = tid >> 1, bKt = (tid & 1) << 3;        // NT: n-row 0..127, 8 k

    for (int k0 = 0; k0 < K; k0 += 16) {
        {
            const float* ap = A + (long long)(row0 + aRow) * lda + k0 + aK;
            float4 a0 = *(const float4*)(ap);
            float4 a1 = *(const float4*)(ap + 4);
            As[aK + 0][aRow] = a0.x;  As[aK + 1][aRow] = a0.y;
            As[aK + 2][aRow] = a0.z;  As[aK + 3][aRow] = a0.w;
            As[aK + 4][aRow] = a1.x;  As[aK + 5][aRow] = a1.y;
            As[aK + 6][aRow] = a1.z;  As[aK + 7][aRow] = a1.w;
        }
        if (!transB) {
            const float* bp = B + (long long)(k0 + bKn) * ldb + col0 + bNn;
            float4 b0 = *(const float4*)(bp);
            float4 b1 = *(const float4*)(bp + 4);
            *(float4*)&Bs[bKn][bNn]     = b0;
            *(float4*)&Bs[bKn][bNn + 4] = b1;
        } else {
            const float* bp = B + (long long)(col0 + bNt) * ldb + k0 + bKt;
            float4 b0 = *(const float4*)(bp);
            float4 b1 = *(const float4*)(bp + 4);
            Bs[bKt + 0][bNt] = b0.x;  Bs[bKt + 1][bNt] = b0.y;
            Bs[bKt + 2][bNt] = b0.z;  Bs[bKt + 3][bNt] = b0.w;
            Bs[bKt + 4][bNt] = b1.x;  Bs[bKt + 5][bNt] = b1.y;
            Bs[bKt + 6][bNt] = b1.z;  Bs[bKt + 7][bNt] = b1.w;
        }
        __syncthreads();

#pragma unroll
        for (int kk = 0; kk < 16; kk++) {
            float4 a0 = *(const float4*)&As[kk][ty * 8];
            float4 a1 = *(const float4*)&As[kk][ty * 8 + 4];
            float4 b0 = *(const float4*)&Bs[kk][tx * 8];
            float4 b1 = *(const float4*)&Bs[kk][tx * 8 + 4];
            float ar[8] = {a0.x, a0.y, a0.z, a0.w, a1.x, a1.y, a1.z, a1.w};
            float br[8] = {b0.x, b0.y, b0.z, b0.w, b1.x, b1.y, b1.z, b1.w};
#pragma unroll
            for (int i = 0; i < 8; i++)
#pragma unroll
                for (int j = 0; j < 8; j++) acc[i][j] += ar[i] * br[j];
        }
        __syncthreads();
    }

#pragma unroll
    for (int i = 0; i < 8; i++) {
        int r = row0 + ty * 8 + i;
#pragma unroll
        for (int j = 0; j < 8; j++) {
            int c = col0 + tx * 8 + j;
            float v = acc[i][j] * alpha;
            if (MASK) v += MASK[(long long)r * mld + c];
            if (ADD)  v += ADD[(long long)r * ldc + c];
            C[(long long)r * ldc + c] = v;
        }
    }
}

static inline void launch_gemm(const float* A, const float* B, float* C,
                               const float* ADD, const float* MASK,
                               int M, int N, int K, int lda, int ldb, int ldc, int mld,
                               long long sA, long long sB, long long sC,
                               float alpha, int transB, int batch)
{
    dim3 grid(N / 128, M / 128, batch);
    sgemm_kernel<<<grid, 256>>>(A, B, C, ADD, MASK, K, lda, ldb, ldc, mld,
                                sA, sB, sC, alpha, transB);
}

// ---------------- RMSNorm: y = x * rsqrt(mean(x^2)+eps) * (1+w) ----------------
__global__ void rmsnorm_kernel(const float* __restrict__ x, const float* __restrict__ w,
                               float* __restrict__ y)
{
    int row = blockIdx.x;
    const float* xr = x + (long long)row * HIDN;
    float* yr = y + (long long)row * HIDN;
    int tid = threadIdx.x;

    float ss = 0.0f;
    for (int i = tid; i < HIDN; i += blockDim.x) { float v = xr[i]; ss += v * v; }

    __shared__ float red[32];
#pragma unroll
    for (int o = 16; o; o >>= 1) ss += __shfl_xor_sync(0xffffffffu, ss, o);
    if ((tid & 31) == 0) red[tid >> 5] = ss;
    __syncthreads();
    if (tid < 32) {
        float v = (tid < (int)(blockDim.x >> 5)) ? red[tid] : 0.0f;
#pragma unroll
        for (int o = 16; o; o >>= 1) v += __shfl_xor_sync(0xffffffffu, v, o);
        if (tid == 0) red[0] = v;
    }
    __syncthreads();
    float r = rsqrtf(red[0] / (float)HIDN + 1e-6f);
    for (int i = tid; i < HIDN; i += blockDim.x)
        yr[i] = xr[i] * r * (1.0f + w[i]);
}

// ---------------- RoPE ----------------
// src: head stride SQ2*HDIM (concat buffer, expert offset pre-applied), row stride HDIM
// dst: compact per-expert [h][s][d]
__global__ void rope_kernel(const float* __restrict__ src, float* __restrict__ dst)
{
    int s = blockIdx.x, h = blockIdx.y, d = threadIdx.x;
    const float* x = src + (long long)h * SQ2 * HDIM + (long long)s * HDIM;
    float* y = dst + (long long)h * SQ * HDIM + (long long)s * HDIM;

    int i = d & 63;
    double inv = exp(-(double)i * (log(10000.0) / 64.0));
    double ang = (double)s * inv;
    double sn, cs;
    sincos(ang, &sn, &cs);

    float xv  = x[d];
    float rot = (d < 64) ? -x[d + 64] : x[d - 64];
    y[d] = xv * (float)cs + rot * (float)sn;
}

// ---------------- row softmax (in place) ----------------
__global__ void softmax_kernel(float* __restrict__ S, int N)
{
    long long row = blockIdx.x;
    float* p = S + row * (long long)N;
    int tid = threadIdx.x;
    __shared__ float red[32];

    float m = -1e30f;
    for (int i = tid; i < N; i += blockDim.x) m = fmaxf(m, p[i]);
#pragma unroll
    for (int o = 16; o; o >>= 1) m = fmaxf(m, __shfl_xor_sync(0xffffffffu, m, o));
    if ((tid & 31) == 0) red[tid >> 5] = m;
    __syncthreads();
    if (tid < 32) {
        float v = (tid < (int)(blockDim.x >> 5)) ? red[tid] : -1e30f;
#pragma unroll
        for (int o = 16; o; o >>= 1) v = fmaxf(v, __shfl_xor_sync(0xffffffffu, v, o));
        if (tid == 0) red[0] = v;
    }
    __syncthreads();
    m = red[0];
    __syncthreads();

    float s = 0.0f;
    for (int i = tid; i < N; i += blockDim.x) {
        float e = __expf(p[i] - m);
        p[i] = e;
        s += e;
    }
#pragma unroll
    for (int o = 16; o; o >>= 1) s += __shfl_xor_sync(0xffffffffu, s, o);
    __syncthreads();
    if ((tid & 31) == 0) red[tid >> 5] = s;
    __syncthreads();
    if (tid < 32) {
        float v = (tid < (int)(blockDim.x >> 5)) ? red[tid] : 0.0f;
#pragma unroll
        for (int o = 16; o; o >>= 1) v += __shfl_xor_sync(0xffffffffu, v, o);
        if (tid == 0) red[0] = v;
    }
    __syncthreads();
    float inv = 1.0f / red[0];
    for (int i = tid; i < N; i += blockDim.x) p[i] *= inv;
}

// ---------------- gelu(gate)*up, in place into gate ----------------
__global__ void gelumul_kernel(float* __restrict__ g, const float* __restrict__ u, long long n)
{
    long long i = (long long)blockIdx.x * blockDim.x + threadIdx.x;
    if (i < n) {
        float x = g[i];
        float t = tanhf(0.7978845608028654f * (x + 0.044715f * x * x * x));
        g[i] = 0.5f * x * (1.0f + t) * u[i];
    }
}

// ---------------- host orchestration ----------------
extern "C" void kernel_launch(void* const* d_in, const int* in_sizes, int n_in,
                              void* d_out, int out_size)
{
    (void)in_sizes; (void)n_in; (void)out_size;

    const float* x[2]    = { (const float*)d_in[0], (const float*)d_in[1] };
    const float* mask[2] = { (const float*)d_in[2], (const float*)d_in[3] };
    const float* mixmask =   (const float*)d_in[4];

    struct W { const float *ln, *q, *k, *v, *o, *pln, *g, *u, *d; } wts[2];
    for (int e = 0; e < 2; e++) {
        int b = 5 + e * 9;
        wts[e].ln  = (const float*)d_in[b + 0];
        wts[e].q   = (const float*)d_in[b + 1];
        wts[e].k   = (const float*)d_in[b + 2];
        wts[e].v   = (const float*)d_in[b + 3];
        wts[e].o   = (const float*)d_in[b + 4];
        wts[e].pln = (const float*)d_in[b + 5];
        wts[e].g   = (const float*)d_in[b + 6];
        wts[e].u   = (const float*)d_in[b + 7];
        wts[e].d   = (const float*)d_in[b + 8];
    }

    float *h, *h1, *qc, *kc, *vc, *qr, *kr, *sc, *am, *gt, *up, *oe;
    cudaGetSymbolAddress((void**)&h,  g_h);
    cudaGetSymbolAddress((void**)&h1, g_h1);
    cudaGetSymbolAddress((void**)&qc, g_qc);
    cudaGetSymbolAddress((void**)&kc, g_kc);
    cudaGetSymbolAddress((void**)&vc, g_vc);
    cudaGetSymbolAddress((void**)&qr, g_qr);
    cudaGetSymbolAddress((void**)&kr, g_kr);
    cudaGetSymbolAddress((void**)&sc, g_scores);
    cudaGetSymbolAddress((void**)&am, g_attnM);
    cudaGetSymbolAddress((void**)&gt, g_gate);
    cudaGetSymbolAddress((void**)&up, g_up);
    cudaGetSymbolAddress((void**)&oe, g_oute);

    const float SCALE = 0.08838834764831845f;   // 1/sqrt(128)
    float* out = (float*)d_out;

    for (int e = 0; e < 2; e++) {
        // h = rms_norm(x, w_ln)
        rmsnorm_kernel<<<SQ, 256>>>(x[e], wts[e].ln, h);

        // q/k/v projections, stored directly in concat layout [h][e*S+s][d]
        // batch = head; B slice via column offset 128; C stride SQ2*HDIM
        launch_gemm(h, wts[e].q, qc + (long long)e * SQ * HDIM, nullptr, nullptr,
                    SQ, HDIM, HIDN, HIDN, HIDN, HDIM, 0,
                    0, 128, (long long)SQ2 * HDIM, 1.0f, 0, NHEAD);
        launch_gemm(h, wts[e].k, kc + (long long)e * SQ * HDIM, nullptr, nullptr,
                    SQ, HDIM, HIDN, HIDN, HIDN, HDIM, 0,
                    0, 128, (long long)SQ2 * HDIM, 1.0f, 0, NHEAD);
        launch_gemm(h, wts[e].v, vc + (long long)e * SQ * HDIM, nullptr, nullptr,
                    SQ, HDIM, HIDN, HIDN, HIDN, HDIM, 0,
                    0, 128, (long long)SQ2 * HDIM, 1.0f, 0, NHEAD);

        // RoPE q,k -> compact per-expert buffers
        rope_kernel<<<dim3(SQ, NHEAD), HDIM>>>(qc + (long long)e * SQ * HDIM, qr);
        rope_kernel<<<dim3(SQ, NHEAD), HDIM>>>(kc + (long long)e * SQ * HDIM, kr);

        // scores = qr @ kr^T * scale + causal mask (batched over heads)
        launch_gemm(qr, kr, sc, nullptr, mask[e],
                    SQ, SQ, HDIM, HDIM, HDIM, SQ, SQ,
                    (long long)SQ * HDIM, (long long)SQ * HDIM, (long long)SQ * SQ,
                    SCALE, 1, NHEAD);
        softmax_kernel<<<NHEAD * SQ, 256>>>(sc, SQ);

        // attn = P @ V, stored head-merged into (S, 1024)
        launch_gemm(sc, vc + (long long)e * SQ * HDIM, am, nullptr, nullptr,
                    SQ, HDIM, SQ, SQ, HDIM, HIDN, 0,
                    (long long)SQ * SQ, (long long)SQ2 * HDIM, HDIM,
                    1.0f, 0, NHEAD);

        // h1 = x + attn @ w_o
        launch_gemm(am, wts[e].o, h1, x[e], nullptr,
                    SQ, HIDN, HIDN, HIDN, HIDN, HIDN, 0,
                    0, 0, 0, 1.0f, 0, 1);

        // m = rms_norm(h1, w_pln)
        rmsnorm_kernel<<<SQ, 256>>>(h1, wts[e].pln, h);

        // MLP
        launch_gemm(h, wts[e].g, gt, nullptr, nullptr,
                    SQ, INTERN, HIDN, HIDN, INTERN, INTERN, 0,
                    0, 0, 0, 1.0f, 0, 1);
        launch_gemm(h, wts[e].u, up, nullptr, nullptr,
                    SQ, INTERN, HIDN, HIDN, INTERN, INTERN, 0,
                    0, 0, 0, 1.0f, 0, 1);
        {
            long long n = (long long)SQ * INTERN;
            int thr = 256;
            long long blk = (n + thr - 1) / thr;
            gelumul_kernel<<<(unsigned)blk, thr>>>(gt, up, n);
        }
        // out_e = h1 + act @ w_d
        launch_gemm(gt, wts[e].d, oe + (long long)e * SQ * HIDN, h1, nullptr,
                    SQ, HIDN, INTERN, INTERN, HIDN, HIDN, 0,
                    0, 0, 0, 1.0f, 0, 1);
    }

    // ---- mix attention over concatenated pre-RoPE q/k/v ----
    launch_gemm(qc, kc, sc, nullptr, mixmask,
                SQ2, SQ2, HDIM, HDIM, HDIM, SQ2, SQ2,
                (long long)SQ2 * HDIM, (long long)SQ2 * HDIM, (long long)SQ2 * SQ2,
                SCALE, 1, NHEAD);
    softmax_kernel<<<NHEAD * SQ2, 256>>>(sc, SQ2);
    launch_gemm(sc, vc, am, nullptr, nullptr,
                SQ2, HDIM, SQ2, SQ2, HDIM, HIDN, 0,
                (long long)SQ2 * SQ2, (long long)SQ2 * HDIM, HDIM,
                1.0f, 0, NHEAD);

    // out[0] = out_a + ma @ w_o_a ; out[1] = out_b + mb @ w_o_b
    launch_gemm(am, wts[0].o, out, oe, nullptr,
                SQ, HIDN, HIDN, HIDN, HIDN, HIDN, 0,
                0, 0, 0, 1.0f, 0, 1);
    launch_gemm(am + (long long)SQ * HIDN, wts[1].o, out + (long long)SQ * HIDN,
                oe + (long long)SQ * HIDN, nullptr,
                SQ, HIDN, HIDN, HIDN, HIDN, HIDN, 0,
                0, 0, 0, 1.0f, 0, 1);
}

// round 8
// speedup vs baseline: 1.2883x; 1.2883x over previous
#include <cuda_runtime.h>
#include <cuda_bf16.h>
#include <math.h>

// Problem constants
#define SQ    2048
#define SQ2   4096
#define HIDN  1024
#define NHEAD 8
#define HDIM  128
#define INTERN 4096

// ---------------- scratch (device globals; no allocations allowed) ----------------
__device__ float g_h   [SQ  * HIDN];
__device__ float g_h1  [SQ  * HIDN];
__device__ float g_qc  [NHEAD * SQ2 * HDIM];
__device__ float g_kc  [NHEAD * SQ2 * HDIM];
__device__ float g_vc  [NHEAD * SQ2 * HDIM];
__device__ float g_qr  [NHEAD * SQ  * HDIM];
__device__ float g_kr  [NHEAD * SQ  * HDIM];
__device__ float g_scores[(size_t)NHEAD * SQ2 * SQ2];
__device__ float g_attnM[SQ2 * HIDN];
__device__ float g_gate[SQ * INTERN];
__device__ float g_up  [SQ * INTERN];
__device__ float g_oute[2 * SQ * HIDN];

// ---------------- bf16-split tensor-core GEMM ----------------
// C[bz] = alpha * A[bz] @ op(B[bz]) (+ MASK) (+ ADD)
// fp32 emulated as A_hi+A_lo / B_hi+B_lo bf16 pairs; 3 mma terms, fp32 accum.
// Block tile 128x128, K-tile 32, 8 warps (each 64x32), mma.m16n8k16.
// Requires: M,N multiples of 128; K multiple of 32. (True for all calls.)

#define SWH 40   // smem tile row stride in halfs (20 words -> conflict-free frags)

__device__ __forceinline__ void bf16_split(float x, __nv_bfloat16& h, __nv_bfloat16& l)
{
    h = __float2bfloat16_rn(x);
    l = __float2bfloat16_rn(x - __bfloat162float(h));
}

__device__ __forceinline__ void mma_bf16(float* c, const unsigned* a, const unsigned* b)
{
    asm volatile(
        "mma.sync.aligned.m16n8k16.row.col.f32.bf16.bf16.f32 "
        "{%0,%1,%2,%3}, {%4,%5,%6,%7}, {%8,%9}, {%0,%1,%2,%3};"
        : "+f"(c[0]), "+f"(c[1]), "+f"(c[2]), "+f"(c[3])
        : "r"(a[0]), "r"(a[1]), "r"(a[2]), "r"(a[3]), "r"(b[0]), "r"(b[1]));
}

__global__ void __launch_bounds__(256) sgemm_kernel(
    const float* __restrict__ A, const float* __restrict__ B, float* __restrict__ C,
    const float* __restrict__ ADD, const float* __restrict__ MASK,
    int K, int lda, int ldb, int ldc, int mld,
    long long sA, long long sB, long long sC,
    float alpha, int transB)
{
    int bz = blockIdx.z;
    A += (long long)bz * sA;
    B += (long long)bz * sB;
    C += (long long)bz * sC;

    __shared__ __nv_bfloat16 Ahi[128][SWH];
    __shared__ __nv_bfloat16 Alo[128][SWH];
    __shared__ __nv_bfloat16 Bhi[128][SWH];
    __shared__ __nv_bfloat16 Blo[128][SWH];

    const unsigned* Ah32 = (const unsigned*)&Ahi[0][0];
    const unsigned* Al32 = (const unsigned*)&Alo[0][0];
    const unsigned* Bh32 = (const unsigned*)&Bhi[0][0];
    const unsigned* Bl32 = (const unsigned*)&Blo[0][0];

    int tid  = threadIdx.x;
    int lane = tid & 31;
    int wid  = tid >> 5;
    int g    = lane >> 2;          // 0..7
    int t    = lane & 3;           // 0..3
    int wm   = (wid >> 2) * 64;    // warp m offset (0/64)
    int wn   = (wid & 3) * 32;     // warp n offset (0/32/64/96)
    int row0 = blockIdx.y << 7;
    int col0 = blockIdx.x << 7;

    float acc[4][4][4];
#pragma unroll
    for (int mi = 0; mi < 4; mi++)
#pragma unroll
        for (int ni = 0; ni < 4; ni++)
#pragma unroll
            for (int q = 0; q < 4; q++) acc[mi][ni][q] = 0.0f;

    // loader indices
    int ar = tid >> 1, ak = (tid & 1) << 4;   // A / B-NT: row, k base (0/16)
    int bk = tid >> 3, bn = (tid & 7) << 4;   // B-NN: k row, n base

    for (int k0 = 0; k0 < K; k0 += 32) {
        // ---- load & split A tile (128 x 32), store m-major ----
        {
            const float* ap = A + (long long)(row0 + ar) * lda + k0 + ak;
#pragma unroll
            for (int q = 0; q < 4; q++) {
                float4 v = *(const float4*)(ap + 4 * q);
                __nv_bfloat16 h0, h1, h2, h3, l0, l1, l2, l3;
                bf16_split(v.x, h0, l0); bf16_split(v.y, h1, l1);
                bf16_split(v.z, h2, l2); bf16_split(v.w, h3, l3);
                int kc = ak + 4 * q;
                *(__nv_bfloat162*)&Ahi[ar][kc]     = __halves2bfloat162(h0, h1);
                *(__nv_bfloat162*)&Ahi[ar][kc + 2] = __halves2bfloat162(h2, h3);
                *(__nv_bfloat162*)&Alo[ar][kc]     = __halves2bfloat162(l0, l1);
                *(__nv_bfloat162*)&Alo[ar][kc + 2] = __halves2bfloat162(l2, l3);
            }
        }
        // ---- load & split B tile, store n-major [n][k] ----
        if (!transB) {
            const float* bp = B + (long long)(k0 + bk) * ldb + col0 + bn;
#pragma unroll
            for (int q = 0; q < 4; q++) {
                float4 v = *(const float4*)(bp + 4 * q);
                int nc = bn + 4 * q;
                __nv_bfloat16 h, l;
                bf16_split(v.x, h, l); Bhi[nc + 0][bk] = h; Blo[nc + 0][bk] = l;
                bf16_split(v.y, h, l); Bhi[nc + 1][bk] = h; Blo[nc + 1][bk] = l;
                bf16_split(v.z, h, l); Bhi[nc + 2][bk] = h; Blo[nc + 2][bk] = l;
                bf16_split(v.w, h, l); Bhi[nc + 3][bk] = h; Blo[nc + 3][bk] = l;
            }
        } else {
            const float* bp = B + (long long)(col0 + ar) * ldb + k0 + ak;
#pragma unroll
            for (int q = 0; q < 4; q++) {
                float4 v = *(const float4*)(bp + 4 * q);
                __nv_bfloat16 h0, h1, h2, h3, l0, l1, l2, l3;
                bf16_split(v.x, h0, l0); bf16_split(v.y, h1, l1);
                bf16_split(v.z, h2, l2); bf16_split(v.w, h3, l3);
                int kc = ak + 4 * q;
                *(__nv_bfloat162*)&Bhi[ar][kc]     = __halves2bfloat162(h0, h1);
                *(__nv_bfloat162*)&Bhi[ar][kc + 2] = __halves2bfloat162(h2, h3);
                *(__nv_bfloat162*)&Blo[ar][kc]     = __halves2bfloat162(l0, l1);
                *(__nv_bfloat162*)&Blo[ar][kc + 2] = __halves2bfloat162(l2, l3);
            }
        }
        __syncthreads();

#pragma unroll
        for (int kk = 0; kk < 2; kk++) {
            const int kw = kk * 8;
            unsigned af[4][4];
            unsigned bfr[4][2];

            // term 1: A_hi x B_hi
#pragma unroll
            for (int mi = 0; mi < 4; mi++) {
                int r0 = (wm + mi * 16 + g) * 20 + kw + t;
                af[mi][0] = Ah32[r0];
                af[mi][1] = Ah32[r0 + 160];   // +8 rows * 20 words
                af[mi][2] = Ah32[r0 + 4];
                af[mi][3] = Ah32[r0 + 164];
            }
#pragma unroll
            for (int ni = 0; ni < 4; ni++) {
                int n0 = (wn + ni * 8 + g) * 20 + kw + t;
                bfr[ni][0] = Bh32[n0];
                bfr[ni][1] = Bh32[n0 + 4];
            }
#pragma unroll
            for (int mi = 0; mi < 4; mi++)
#pragma unroll
                for (int ni = 0; ni < 4; ni++)
                    mma_bf16(acc[mi][ni], af[mi], bfr[ni]);

            // term 2: A_hi x B_lo (reuse af)
#pragma unroll
            for (int ni = 0; ni < 4; ni++) {
                int n0 = (wn + ni * 8 + g) * 20 + kw + t;
                bfr[ni][0] = Bl32[n0];
                bfr[ni][1] = Bl32[n0 + 4];
            }
#pragma unroll
            for (int mi = 0; mi < 4; mi++)
#pragma unroll
                for (int ni = 0; ni < 4; ni++)
                    mma_bf16(acc[mi][ni], af[mi], bfr[ni]);

            // term 3: A_lo x B_hi
#pragma unroll
            for (int mi = 0; mi < 4; mi++) {
                int r0 = (wm + mi * 16 + g) * 20 + kw + t;
                af[mi][0] = Al32[r0];
                af[mi][1] = Al32[r0 + 160];
                af[mi][2] = Al32[r0 + 4];
                af[mi][3] = Al32[r0 + 164];
            }
#pragma unroll
            for (int ni = 0; ni < 4; ni++) {
                int n0 = (wn + ni * 8 + g) * 20 + kw + t;
                bfr[ni][0] = Bh32[n0];
                bfr[ni][1] = Bh32[n0 + 4];
            }
#pragma unroll
            for (int mi = 0; mi < 4; mi++)
#pragma unroll
                for (int ni = 0; ni < 4; ni++)
                    mma_bf16(acc[mi][ni], af[mi], bfr[ni]);
        }
        __syncthreads();
    }

    // ---- epilogue ----
#pragma unroll
    for (int mi = 0; mi < 4; mi++) {
#pragma unroll
        for (int ni = 0; ni < 4; ni++) {
            int r = row0 + wm + mi * 16 + g;
            int c = col0 + wn + ni * 8 + 2 * t;
            float2 v0, v1;
            v0.x = acc[mi][ni][0] * alpha; v0.y = acc[mi][ni][1] * alpha;
            v1.x = acc[mi][ni][2] * alpha; v1.y = acc[mi][ni][3] * alpha;
            if (MASK) {
                v0.x += MASK[(long long)r * mld + c];
                v0.y += MASK[(long long)r * mld + c + 1];
                v1.x += MASK[(long long)(r + 8) * mld + c];
                v1.y += MASK[(long long)(r + 8) * mld + c + 1];
            }
            if (ADD) {
                v0.x += ADD[(long long)r * ldc + c];
                v0.y += ADD[(long long)r * ldc + c + 1];
                v1.x += ADD[(long long)(r + 8) * ldc + c];
                v1.y += ADD[(long long)(r + 8) * ldc + c + 1];
            }
            *(float2*)&C[(long long)r * ldc + c]       = v0;
            *(float2*)&C[(long long)(r + 8) * ldc + c] = v1;
        }
    }
}

static inline void launch_gemm(const float* A, const float* B, float* C,
                               const float* ADD, const float* MASK,
                               int M, int N, int K, int lda, int ldb, int ldc, int mld,
                               long long sA, long long sB, long long sC,
                               float alpha, int transB, int batch)
{
    dim3 grid(N / 128, M / 128, batch);
    sgemm_kernel<<<grid, 256>>>(A, B, C, ADD, MASK, K, lda, ldb, ldc, mld,
                                sA, sB, sC, alpha, transB);
}

// ---------------- RMSNorm ----------------
__global__ void rmsnorm_kernel(const float* __restrict__ x, const float* __restrict__ w,
                               float* __restrict__ y)
{
    int row = blockIdx.x;
    const float* xr = x + (long long)row * HIDN;
    float* yr = y + (long long)row * HIDN;
    int tid = threadIdx.x;

    float ss = 0.0f;
    for (int i = tid; i < HIDN; i += blockDim.x) { float v = xr[i]; ss += v * v; }

    __shared__ float red[32];
#pragma unroll
    for (int o = 16; o; o >>= 1) ss += __shfl_xor_sync(0xffffffffu, ss, o);
    if ((tid & 31) == 0) red[tid >> 5] = ss;
    __syncthreads();
    if (tid < 32) {
        float v = (tid < (int)(blockDim.x >> 5)) ? red[tid] : 0.0f;
#pragma unroll
        for (int o = 16; o; o >>= 1) v += __shfl_xor_sync(0xffffffffu, v, o);
        if (tid == 0) red[0] = v;
    }
    __syncthreads();
    float r = rsqrtf(red[0] / (float)HIDN + 1e-6f);
    for (int i = tid; i < HIDN; i += blockDim.x)
        yr[i] = xr[i] * r * (1.0f + w[i]);
}

// ---------------- RoPE ----------------
__global__ void rope_kernel(const float* __restrict__ src, float* __restrict__ dst)
{
    int s = blockIdx.x, h = blockIdx.y, d = threadIdx.x;
    const float* x = src + (long long)h * SQ2 * HDIM + (long long)s * HDIM;
    float* y = dst + (long long)h * SQ * HDIM + (long long)s * HDIM;

    int i = d & 63;
    double inv = exp(-(double)i * (log(10000.0) / 64.0));
    double ang = (double)s * inv;
    double sn, cs;
    sincos(ang, &sn, &cs);

    float xv  = x[d];
    float rot = (d < 64) ? -x[d + 64] : x[d - 64];
    y[d] = xv * (float)cs + rot * (float)sn;
}

// ---------------- row softmax (in place) ----------------
__global__ void softmax_kernel(float* __restrict__ S, int N)
{
    long long row = blockIdx.x;
    float* p = S + row * (long long)N;
    int tid = threadIdx.x;
    __shared__ float red[32];

    float m = -1e30f;
    for (int i = tid; i < N; i += blockDim.x) m = fmaxf(m, p[i]);
#pragma unroll
    for (int o = 16; o; o >>= 1) m = fmaxf(m, __shfl_xor_sync(0xffffffffu, m, o));
    if ((tid & 31) == 0) red[tid >> 5] = m;
    __syncthreads();
    if (tid < 32) {
        float v = (tid < (int)(blockDim.x >> 5)) ? red[tid] : -1e30f;
#pragma unroll
        for (int o = 16; o; o >>= 1) v = fmaxf(v, __shfl_xor_sync(0xffffffffu, v, o));
        if (tid == 0) red[0] = v;
    }
    __syncthreads();
    m = red[0];
    __syncthreads();

    float s = 0.0f;
    for (int i = tid; i < N; i += blockDim.x) {
        float e = __expf(p[i] - m);
        p[i] = e;
        s += e;
    }
#pragma unroll
    for (int o = 16; o; o >>= 1) s += __shfl_xor_sync(0xffffffffu, s, o);
    __syncthreads();
    if ((tid & 31) == 0) red[tid >> 5] = s;
    __syncthreads();
    if (tid < 32) {
        float v = (tid < (int)(blockDim.x >> 5)) ? red[tid] : 0.0f;
#pragma unroll
        for (int o = 16; o; o >>= 1) v += __shfl_xor_sync(0xffffffffu, v, o);
        if (tid == 0) red[0] = v;
    }
    __syncthreads();
    float inv = 1.0f / red[0];
    for (int i = tid; i < N; i += blockDim.x) p[i] *= inv;
}

// ---------------- gelu(gate)*up, in place into gate ----------------
__global__ void gelumul_kernel(float* __restrict__ g, const float* __restrict__ u, long long n)
{
    long long i = (long long)blockIdx.x * blockDim.x + threadIdx.x;
    if (i < n) {
        float x = g[i];
        float t = tanhf(0.7978845608028654f * (x + 0.044715f * x * x * x));
        g[i] = 0.5f * x * (1.0f + t) * u[i];
    }
}

// ---------------- host orchestration ----------------
extern "C" void kernel_launch(void* const* d_in, const int* in_sizes, int n_in,
                              void* d_out, int out_size)
{
    (void)in_sizes; (void)n_in; (void)out_size;

    const float* x[2]    = { (const float*)d_in[0], (const float*)d_in[1] };
    const float* mask[2] = { (const float*)d_in[2], (const float*)d_in[3] };
    const float* mixmask =   (const float*)d_in[4];

    struct W { const float *ln, *q, *k, *v, *o, *pln, *g, *u, *d; } wts[2];
    for (int e = 0; e < 2; e++) {
        int b = 5 + e * 9;
        wts[e].ln  = (const float*)d_in[b + 0];
        wts[e].q   = (const float*)d_in[b + 1];
        wts[e].k   = (const float*)d_in[b + 2];
        wts[e].v   = (const float*)d_in[b + 3];
        wts[e].o   = (const float*)d_in[b + 4];
        wts[e].pln = (const float*)d_in[b + 5];
        wts[e].g   = (const float*)d_in[b + 6];
        wts[e].u   = (const float*)d_in[b + 7];
        wts[e].d   = (const float*)d_in[b + 8];
    }

    float *h, *h1, *qc, *kc, *vc, *qr, *kr, *sc, *am, *gt, *up, *oe;
    cudaGetSymbolAddress((void**)&h,  g_h);
    cudaGetSymbolAddress((void**)&h1, g_h1);
    cudaGetSymbolAddress((void**)&qc, g_qc);
    cudaGetSymbolAddress((void**)&kc, g_kc);
    cudaGetSymbolAddress((void**)&vc, g_vc);
    cudaGetSymbolAddress((void**)&qr, g_qr);
    cudaGetSymbolAddress((void**)&kr, g_kr);
    cudaGetSymbolAddress((void**)&sc, g_scores);
    cudaGetSymbolAddress((void**)&am, g_attnM);
    cudaGetSymbolAddress((void**)&gt, g_gate);
    cudaGetSymbolAddress((void**)&up, g_up);
    cudaGetSymbolAddress((void**)&oe, g_oute);

    const float SCALE = 0.08838834764831845f;   // 1/sqrt(128)
    float* out = (float*)d_out;

    for (int e = 0; e < 2; e++) {
        rmsnorm_kernel<<<SQ, 256>>>(x[e], wts[e].ln, h);

        launch_gemm(h, wts[e].q, qc + (long long)e * SQ * HDIM, nullptr, nullptr,
                    SQ, HDIM, HIDN, HIDN, HIDN, HDIM, 0,
                    0, 128, (long long)SQ2 * HDIM, 1.0f, 0, NHEAD);
        launch_gemm(h, wts[e].k, kc + (long long)e * SQ * HDIM, nullptr, nullptr,
                    SQ, HDIM, HIDN, HIDN, HIDN, HDIM, 0,
                    0, 128, (long long)SQ2 * HDIM, 1.0f, 0, NHEAD);
        launch_gemm(h, wts[e].v, vc + (long long)e * SQ * HDIM, nullptr, nullptr,
                    SQ, HDIM, HIDN, HIDN, HIDN, HDIM, 0,
                    0, 128, (long long)SQ2 * HDIM, 1.0f, 0, NHEAD);

        rope_kernel<<<dim3(SQ, NHEAD), HDIM>>>(qc + (long long)e * SQ * HDIM, qr);
        rope_kernel<<<dim3(SQ, NHEAD), HDIM>>>(kc + (long long)e * SQ * HDIM, kr);

        launch_gemm(qr, kr, sc, nullptr, mask[e],
                    SQ, SQ, HDIM, HDIM, HDIM, SQ, SQ,
                    (long long)SQ * HDIM, (long long)SQ * HDIM, (long long)SQ * SQ,
                    SCALE, 1, NHEAD);
        softmax_kernel<<<NHEAD * SQ, 256>>>(sc, SQ);

        launch_gemm(sc, vc + (long long)e * SQ * HDIM, am, nullptr, nullptr,
                    SQ, HDIM, SQ, SQ, HDIM, HIDN, 0,
                    (long long)SQ * SQ, (long long)SQ2 * HDIM, HDIM,
                    1.0f, 0, NHEAD);

        launch_gemm(am, wts[e].o, h1, x[e], nullptr,
                    SQ, HIDN, HIDN, HIDN, HIDN, HIDN, 0,
                    0, 0, 0, 1.0f, 0, 1);

        rmsnorm_kernel<<<SQ, 256>>>(h1, wts[e].pln, h);

        launch_gemm(h, wts[e].g, gt, nullptr, nullptr,
                    SQ, INTERN, HIDN, HIDN, INTERN, INTERN, 0,
                    0, 0, 0, 1.0f, 0, 1);
        launch_gemm(h, wts[e].u, up, nullptr, nullptr,
                    SQ, INTERN, HIDN, HIDN, INTERN, INTERN, 0,
                    0, 0, 0, 1.0f, 0, 1);
        {
            long long n = (long long)SQ * INTERN;
            int thr = 256;
            long long blk = (n + thr - 1) / thr;
            gelumul_kernel<<<(unsigned)blk, thr>>>(gt, up, n);
        }
        launch_gemm(gt, wts[e].d, oe + (long long)e * SQ * HIDN, h1, nullptr,
                    SQ, HIDN, INTERN, INTERN, HIDN, HIDN, 0,
                    0, 0, 0, 1.0f, 0, 1);
    }

    // ---- mix attention over concatenated pre-RoPE q/k/v ----
    launch_gemm(qc, kc, sc, nullptr, mixmask,
                SQ2, SQ2, HDIM, HDIM, HDIM, SQ2, SQ2,
                (long long)SQ2 * HDIM, (long long)SQ2 * HDIM, (long long)SQ2 * SQ2,
                SCALE, 1, NHEAD);
    softmax_kernel<<<NHEAD * SQ2, 256>>>(sc, SQ2);
    launch_gemm(sc, vc, am, nullptr, nullptr,
                SQ2, HDIM, SQ2, SQ2, HDIM, HIDN, 0,
                (long long)SQ2 * SQ2, (long long)SQ2 * HDIM, HDIM,
                1.0f, 0, NHEAD);

    launch_gemm(am, wts[0].o, out, oe, nullptr,
                SQ, HIDN, HIDN, HIDN, HIDN, HIDN, 0,
                0, 0, 0, 1.0f, 0, 1);
    launch_gemm(am + (long long)SQ * HIDN, wts[1].o, out + (long long)SQ * HIDN,
                oe + (long long)SQ * HIDN, nullptr,
                SQ, HIDN, HIDN, HIDN, HIDN, HIDN, 0,
                0, 0, 0, 1.0f, 0, 1);
}